// round 9
// baseline (speedup 1.0000x reference)
#include <cuda_runtime.h>
#include <cuda_fp16.h>
#include <math.h>

#define DD 128
#define MAXN 50000
#define MAXE 800000

__device__ unsigned g_Ph[MAXN * 64];   // A @ h_n           (f16x2 pairs)
__device__ unsigned g_Qh[MAXN * 64];   // B @ h_n + b1      (f16x2 pairs)
__device__ float    g_agg[MAXN * DD];  // scatter-add target (fp32)
__device__ unsigned g_th[MAXN * 64];   // silu(U1@[h;agg]+c1) (f16x2 pairs)
__device__ int      g_eidx[2 * MAXE];  // normalized int32 edge index
__device__ int      g_is64;            // dtype probe result

__device__ __forceinline__ float fast_silu(float x) {
    float hx = 0.5f * x, t;
    asm("tanh.approx.f32 %0, %1;" : "=f"(t) : "f"(hx));
    return fmaf(hx, t, hx);
}

__device__ __forceinline__ void red_add_v2(float* p, float a, float b) {
    asm volatile("red.global.add.v2.f32 [%0], {%1,%2};"
                 :: "l"(p), "f"(a), "f"(b) : "memory");
}

// pack (lo, hi) fp32 -> f16x2
__device__ __forceinline__ unsigned f16x2(float lo, float hi) {
    unsigned r;
    asm("cvt.rn.f16x2.f32 %0, %1, %2;" : "=r"(r) : "f"(hi), "f"(lo));
    return r;
}
__device__ __forceinline__ float2 unpackh2(unsigned u) {
    __half2 h = *reinterpret_cast<const __half2*>(&u);
    return __half22float2(h);
}

// m16n8k16 f16 mma: A row-major (16x16), B col-major (16x8), fp32 accum
__device__ __forceinline__ void mma_f16(float* c, unsigned a0, unsigned a1,
                                        unsigned a2, unsigned a3,
                                        unsigned b0, unsigned b1) {
    asm volatile(
        "mma.sync.aligned.m16n8k16.row.col.f32.f16.f16.f32 "
        "{%0,%1,%2,%3}, {%4,%5,%6,%7}, {%8,%9}, {%0,%1,%2,%3};"
        : "+f"(c[0]), "+f"(c[1]), "+f"(c[2]), "+f"(c[3])
        : "r"(a0), "r"(a1), "r"(a2), "r"(a3), "r"(b0), "r"(b1));
}

// ---------------------------------------------------------------------------
// Kernel 0a/0b: edge_index dtype probe + normalize to int32
// ---------------------------------------------------------------------------
__global__ void k_detect(const unsigned int* __restrict__ p) {
    if (threadIdx.x == 0) {
        int is64 = 1;
        for (int i = 0; i < 512; i++)
            if (p[2 * i + 1] != 0u) { is64 = 0; break; }
        g_is64 = is64;
    }
}

__global__ __launch_bounds__(256) void k_conv(const void* __restrict__ ei,
                                              int twoE, int N) {
    int i = blockIdx.x * blockDim.x + threadIdx.x;
    if (i >= twoE) return;
    long long v = g_is64 ? ((const long long*)ei)[i]
                         : (long long)((const int*)ei)[i];
    if (v < 0) v = 0;
    if (v >= N) v = N - 1;
    g_eidx[i] = (int)v;
}

// ---------------------------------------------------------------------------
// Kernel 1: by=0 -> Ph = A @ h (f16x2);  by=1 -> Qh = B @ h + b1 (f16x2)
// fp16 MMA, 64-node tiles, 256 thr, persistent, 4 CTAs/SM.
// ---------------------------------------------------------------------------
__global__ __launch_bounds__(256, 4) void k_pq(const float* __restrict__ h,
                                               const float* __restrict__ W1,
                                               const float* __restrict__ b1, int N) {
    extern __shared__ float sm[];
    unsigned* Wu = (unsigned*)sm;          // [128 d][68] half2 pairs of k
    unsigned* Xu = (unsigned*)sm + 8704;   // [64 n][68]
    const int t = threadIdx.x;
    const int by = blockIdx.y;

    for (int idx = t; idx < DD * 64; idx += 256) {
        int d = idx >> 6, kk = idx & 63;
        const float* wr = W1 + (size_t)d * 257 + by * DD + 2 * kk;
        Wu[d * 68 + kk] = f16x2(wr[0], wr[1]);
    }
    const int dp = t & 63, q = t >> 6;
    const int warp = t >> 5, lane = t & 31, g = lane >> 2, tg = lane & 3;
    const int mt = warp >> 1, nh = warp & 1;
    const int row0 = mt * 16 + g;

    const int numTiles = (N + 63) >> 6;
    for (int tile = blockIdx.x; tile < numTiles; tile += gridDim.x) {
        const int n0 = tile << 6;
        __syncthreads();
#pragma unroll 4
        for (int e2 = 0; e2 < 16; e2++) {
            int row = q * 16 + e2;
            int node = n0 + row;
            unsigned v = 0;
            if (node < N) {
                float2 hv = *(const float2*)(h + (size_t)node * DD + 2 * dp);
                v = f16x2(hv.x, hv.y);
            }
            Xu[row * 68 + dp] = v;
        }
        __syncthreads();

        float acc[8][4] = {};
#pragma unroll
        for (int ks = 0; ks < 8; ks++) {
            const int kk = ks * 8 + tg;
            unsigned a0 = Xu[row0 * 68 + kk];
            unsigned a1 = Xu[(row0 + 8) * 68 + kk];
            unsigned a2 = Xu[row0 * 68 + kk + 4];
            unsigned a3 = Xu[(row0 + 8) * 68 + kk + 4];
#pragma unroll
            for (int nt = 0; nt < 8; nt++) {
                const int d = nh * 64 + nt * 8 + g;
                mma_f16(acc[nt], a0, a1, a2, a3, Wu[d * 68 + kk], Wu[d * 68 + kk + 4]);
            }
        }

        const int node0 = n0 + row0, node1 = node0 + 8;
        unsigned* dstArr = by ? g_Qh : g_Ph;
#pragma unroll
        for (int nt = 0; nt < 8; nt++) {
            int d = nh * 64 + nt * 8 + 2 * tg;
            float ba = 0.f, bb = 0.f;
            if (by) { ba = b1[d]; bb = b1[d + 1]; }
            if (node0 < N)
                dstArr[(size_t)node0 * 64 + (d >> 1)] = f16x2(acc[nt][0] + ba, acc[nt][1] + bb);
            if (node1 < N)
                dstArr[(size_t)node1 * 64 + (d >> 1)] = f16x2(acc[nt][2] + ba, acc[nt][3] + bb);
        }
    }
}

// ---------------------------------------------------------------------------
// Kernel 2 (edge): fp16 MMA, 128-edge tiles, 256 thr, 2 CTAs/SM.
// Each warp: 32 edges (two m16 tiles) x 64 d -> every B-fragment load feeds
// two MMAs (halves B smem traffic per edge). Bias folded into acc init.
// smem words: Wu[0,8704) Xu[8704,17408) b2s[17408,17536) sdist[17536,17664)
//             ss[17664,17792) sr[17792,17920)
// ---------------------------------------------------------------------------
__global__ __launch_bounds__(256, 2) void k_edge(const float* __restrict__ coords,
                                                 const float* __restrict__ W1,
                                                 const float* __restrict__ W2,
                                                 const float* __restrict__ b2, int E) {
    extern __shared__ float sm[];
    unsigned* Wu = (unsigned*)sm;            // [128 d][68] half2
    unsigned* Xu = (unsigned*)sm + 8704;     // [128 e][68] half2
    float* b2s   = sm + 17408;               // [128]
    float* sdist = sm + 17536;               // [128]
    int* ss = (int*)(sm + 17664);            // [128]
    int* sr = (int*)(sm + 17792);            // [128]
    const int t = threadIdx.x;

    for (int idx = t; idx < DD * 64; idx += 256) {
        int d = idx >> 6, kk = idx & 63;
        Wu[d * 68 + kk] = f16x2(W2[d * DD + 2 * kk], W2[d * DD + 2 * kk + 1]);
    }
    if (t < DD) b2s[t] = b2[t];

    const int dp = t & 63, q = t >> 6;       // stage1: feature pair x edge quarter
    const float wd0 = W1[(2 * dp) * 257 + 256];
    const float wd1 = W1[(2 * dp + 1) * 257 + 256];
    const int warp = t >> 5, lane = t & 31, g = lane >> 2, tg = lane & 3;
    const int mt = warp >> 1, nh = warp & 1;
    const int row0 = mt * 32 + g;            // rows row0, +8 (tile A), +16, +24 (tile B)

    const int numTiles = (E + 127) >> 7;
    for (int tile = blockIdx.x; tile < numTiles; tile += gridDim.x) {
        const int e0 = tile << 7;
        __syncthreads();
        if (t < 128) {
            int e = e0 + t;
            int s = 0, r = 0;
            float dist = 0.f;
            if (e < E) {
                s = g_eidx[e];
                r = g_eidx[E + e];
                float dx = coords[s * 3 + 0] - coords[r * 3 + 0];
                float dy = coords[s * 3 + 1] - coords[r * 3 + 1];
                float dz = coords[s * 3 + 2] - coords[r * 3 + 2];
                dist = sqrtf(fmaf(dx, dx, fmaf(dy, dy, dz * dz)));
            }
            ss[t] = s; sr[t] = r; sdist[t] = dist;
        }
        __syncthreads();

        // Stage 1: 32 edges x feature pair (2dp, 2dp+1), f16x2 gathers
#pragma unroll 8
        for (int e2 = 0; e2 < 32; e2++) {
            int e = q * 32 + e2;
            int s = ss[e], r = sr[e];
            float dist = sdist[e];
            float2 p  = unpackh2(g_Ph[(size_t)s * 64 + dp]);
            float2 qq = unpackh2(g_Qh[(size_t)r * 64 + dp]);
            float zx = fast_silu(p.x + qq.x + dist * wd0);
            float zy = fast_silu(p.y + qq.y + dist * wd1);
            Xu[e * 68 + dp] = f16x2(zx, zy);
        }
        __syncthreads();

        // MMA: two m16 tiles per warp share every B-fragment load.
        float acc0[8][4], acc1[8][4];
#pragma unroll
        for (int nt = 0; nt < 8; nt++) {
            int d = nh * 64 + nt * 8 + 2 * tg;
            float ba = b2s[d], bb = b2s[d + 1];
            acc0[nt][0] = ba; acc0[nt][1] = bb; acc0[nt][2] = ba; acc0[nt][3] = bb;
            acc1[nt][0] = ba; acc1[nt][1] = bb; acc1[nt][2] = ba; acc1[nt][3] = bb;
        }
#pragma unroll
        for (int ks = 0; ks < 8; ks++) {
            const int kk = ks * 8 + tg;
            unsigned a0 = Xu[row0 * 68 + kk];
            unsigned a1 = Xu[(row0 + 8) * 68 + kk];
            unsigned a2 = Xu[row0 * 68 + kk + 4];
            unsigned a3 = Xu[(row0 + 8) * 68 + kk + 4];
            unsigned a4 = Xu[(row0 + 16) * 68 + kk];
            unsigned a5 = Xu[(row0 + 24) * 68 + kk];
            unsigned a6 = Xu[(row0 + 16) * 68 + kk + 4];
            unsigned a7 = Xu[(row0 + 24) * 68 + kk + 4];
#pragma unroll
            for (int nt = 0; nt < 8; nt++) {
                const int d = nh * 64 + nt * 8 + g;
                unsigned b0 = Wu[d * 68 + kk];
                unsigned b1 = Wu[d * 68 + kk + 4];
                mma_f16(acc0[nt], a0, a1, a2, a3, b0, b1);
                mma_f16(acc1[nt], a4, a5, a6, a7, b0, b1);
            }
        }

        // Epilogue: silu + red.v2 scatter for 4 edge-rows
        const bool ok0 = (e0 + row0) < E;
        const bool ok1 = (e0 + row0 + 8) < E;
        const bool ok2 = (e0 + row0 + 16) < E;
        const bool ok3 = (e0 + row0 + 24) < E;
        const int r0 = sr[row0], r1 = sr[row0 + 8];
        const int r2 = sr[row0 + 16], r3 = sr[row0 + 24];
#pragma unroll
        for (int nt = 0; nt < 8; nt++) {
            int d = nh * 64 + nt * 8 + 2 * tg;
            if (ok0)
                red_add_v2(g_agg + (size_t)r0 * DD + d,
                           fast_silu(acc0[nt][0]), fast_silu(acc0[nt][1]));
            if (ok1)
                red_add_v2(g_agg + (size_t)r1 * DD + d,
                           fast_silu(acc0[nt][2]), fast_silu(acc0[nt][3]));
            if (ok2)
                red_add_v2(g_agg + (size_t)r2 * DD + d,
                           fast_silu(acc1[nt][0]), fast_silu(acc1[nt][1]));
            if (ok3)
                red_add_v2(g_agg + (size_t)r3 * DD + d,
                           fast_silu(acc1[nt][2]), fast_silu(acc1[nt][3]));
        }
    }
}

// ---------------------------------------------------------------------------
// Kernel 3: th = f16x2(silu(U1 @ [h ; agg] + c1)), K=256.
// fp16 MMA, stride 140, 2 CTAs/SM.
// ---------------------------------------------------------------------------
__global__ __launch_bounds__(256, 2) void k_u1(const float* __restrict__ h,
                                               const float* __restrict__ U1,
                                               const float* __restrict__ c1, int N) {
    extern __shared__ float sm[];
    unsigned* Wu = (unsigned*)sm;            // [128 d][140]
    unsigned* Xu = (unsigned*)sm + 128 * 140;// [64 n][140]
    const int t = threadIdx.x;

    for (int idx = t; idx < DD * 128; idx += 256) {
        int d = idx >> 7, kk = idx & 127;
        Wu[d * 140 + kk] = f16x2(U1[(size_t)d * 256 + 2 * kk], U1[(size_t)d * 256 + 2 * kk + 1]);
    }
    const int dp = t & 63, q = t >> 6;
    const int warp = t >> 5, lane = t & 31, g = lane >> 2, tg = lane & 3;
    const int mt = warp >> 1, nh = warp & 1;
    const int row0 = mt * 16 + g;

    const int numTiles = (N + 63) >> 6;
    for (int tile = blockIdx.x; tile < numTiles; tile += gridDim.x) {
        const int n0 = tile << 6;
        __syncthreads();
#pragma unroll 4
        for (int e2 = 0; e2 < 16; e2++) {
            int row = q * 16 + e2;
            int node = n0 + row;
            unsigned vh = 0, va = 0;
            if (node < N) {
                float2 hv = *(const float2*)(h + (size_t)node * DD + 2 * dp);
                float2 av = *(const float2*)(g_agg + (size_t)node * DD + 2 * dp);
                vh = f16x2(hv.x, hv.y);
                va = f16x2(av.x, av.y);
            }
            Xu[row * 140 + dp] = vh;
            Xu[row * 140 + 64 + dp] = va;
        }
        __syncthreads();

        float acc[8][4] = {};
#pragma unroll
        for (int ks = 0; ks < 16; ks++) {
            const int kk = ks * 8 + tg;
            unsigned a0 = Xu[row0 * 140 + kk];
            unsigned a1 = Xu[(row0 + 8) * 140 + kk];
            unsigned a2 = Xu[row0 * 140 + kk + 4];
            unsigned a3 = Xu[(row0 + 8) * 140 + kk + 4];
#pragma unroll
            for (int nt = 0; nt < 8; nt++) {
                const int d = nh * 64 + nt * 8 + g;
                mma_f16(acc[nt], a0, a1, a2, a3, Wu[d * 140 + kk], Wu[d * 140 + kk + 4]);
            }
        }

        const int node0 = n0 + row0, node1 = node0 + 8;
#pragma unroll
        for (int nt = 0; nt < 8; nt++) {
            int d = nh * 64 + nt * 8 + 2 * tg;
            float ca = c1[d], cb = c1[d + 1];
            if (node0 < N)
                g_th[(size_t)node0 * 64 + (d >> 1)] =
                    f16x2(fast_silu(acc[nt][0] + ca), fast_silu(acc[nt][1] + cb));
            if (node1 < N)
                g_th[(size_t)node1 * 64 + (d >> 1)] =
                    f16x2(fast_silu(acc[nt][2] + ca), fast_silu(acc[nt][3] + cb));
        }
    }
}

// ---------------------------------------------------------------------------
// Kernel 4: out = h + U2 @ t + c2, K=128. fp16 MMA, 4 CTAs/SM.
// ---------------------------------------------------------------------------
__global__ __launch_bounds__(256, 4) void k_u2(const float* __restrict__ h,
                                               const float* __restrict__ U2,
                                               const float* __restrict__ c2,
                                               float* __restrict__ out, int N) {
    extern __shared__ float sm[];
    unsigned* Wu = (unsigned*)sm;          // [128][68]
    unsigned* Xu = (unsigned*)sm + 8704;   // [64][68]
    const int t = threadIdx.x;

    for (int idx = t; idx < DD * 64; idx += 256) {
        int d = idx >> 6, kk = idx & 63;
        Wu[d * 68 + kk] = f16x2(U2[(size_t)d * DD + 2 * kk], U2[(size_t)d * DD + 2 * kk + 1]);
    }
    const int dp = t & 63, q = t >> 6;
    const int warp = t >> 5, lane = t & 31, g = lane >> 2, tg = lane & 3;
    const int mt = warp >> 1, nh = warp & 1;
    const int row0 = mt * 16 + g;

    const int numTiles = (N + 63) >> 6;
    for (int tile = blockIdx.x; tile < numTiles; tile += gridDim.x) {
        const int n0 = tile << 6;
        __syncthreads();
#pragma unroll 4
        for (int e2 = 0; e2 < 16; e2++) {
            int row = q * 16 + e2;
            int node = n0 + row;
            Xu[row * 68 + dp] = (node < N) ? g_th[(size_t)node * 64 + dp] : 0u;
        }
        __syncthreads();

        float acc[8][4] = {};
#pragma unroll
        for (int ks = 0; ks < 8; ks++) {
            const int kk = ks * 8 + tg;
            unsigned a0 = Xu[row0 * 68 + kk];
            unsigned a1 = Xu[(row0 + 8) * 68 + kk];
            unsigned a2 = Xu[row0 * 68 + kk + 4];
            unsigned a3 = Xu[(row0 + 8) * 68 + kk + 4];
#pragma unroll
            for (int nt = 0; nt < 8; nt++) {
                const int d = nh * 64 + nt * 8 + g;
                mma_f16(acc[nt], a0, a1, a2, a3, Wu[d * 68 + kk], Wu[d * 68 + kk + 4]);
            }
        }

        const int node0 = n0 + row0, node1 = node0 + 8;
#pragma unroll
        for (int nt = 0; nt < 8; nt++) {
            int d = nh * 64 + nt * 8 + 2 * tg;
            float ca = c2[d], cb = c2[d + 1];
            if (node0 < N) {
                float2 hv = *(const float2*)(h + (size_t)node0 * DD + d);
                *(float2*)(out + (size_t)node0 * DD + d) =
                    make_float2(hv.x + acc[nt][0] + ca, hv.y + acc[nt][1] + cb);
            }
            if (node1 < N) {
                float2 hv = *(const float2*)(h + (size_t)node1 * DD + d);
                *(float2*)(out + (size_t)node1 * DD + d) =
                    make_float2(hv.x + acc[nt][2] + ca, hv.y + acc[nt][3] + cb);
            }
        }
    }
}

// ---------------------------------------------------------------------------
extern "C" void kernel_launch(void* const* d_in, const int* in_sizes, int n_in,
                              void* d_out, int out_size) {
    const float* h        = (const float*)d_in[0];
    const float* coords   = (const float*)d_in[1];
    const void*  ei       = d_in[2];
    const float* W1       = (const float*)d_in[3];
    const float* b1       = (const float*)d_in[4];
    const float* W2       = (const float*)d_in[5];
    const float* b2       = (const float*)d_in[6];
    const float* U1       = (const float*)d_in[7];
    const float* c1       = (const float*)d_in[8];
    const float* U2       = (const float*)d_in[9];
    const float* c2       = (const float*)d_in[10];
    float* out = (float*)d_out;

    const int N = in_sizes[0] / DD;
    const int E = in_sizes[2] / 2;

    const size_t sm_pq = (8704 + 64 * 68) * sizeof(unsigned);
    const size_t sm_e  = 17920 * sizeof(float);                          // 71.7 KB
    const size_t sm_u1 = (128 * 140 + 64 * 140) * sizeof(unsigned);      // 105 KB
    const size_t sm_u2 = (8704 + 64 * 68) * sizeof(unsigned);

    cudaFuncSetAttribute(k_pq,   cudaFuncAttributeMaxDynamicSharedMemorySize, (int)sm_pq);
    cudaFuncSetAttribute(k_edge, cudaFuncAttributeMaxDynamicSharedMemorySize, (int)sm_e);
    cudaFuncSetAttribute(k_u1,   cudaFuncAttributeMaxDynamicSharedMemorySize, (int)sm_u1);
    cudaFuncSetAttribute(k_u2,   cudaFuncAttributeMaxDynamicSharedMemorySize, (int)sm_u2);

    void* aggPtr = nullptr;
    cudaGetSymbolAddress(&aggPtr, g_agg);
    cudaMemsetAsync(aggPtr, 0, (size_t)N * DD * sizeof(float));

    const int nodeTiles = (N + 63) / 64;
    const int edgeTiles = (E + 127) / 128;
    const int edgeGrid = edgeTiles < 296 ? edgeTiles : 296;  // 2 CTAs/SM persistent
    const int pqGrid   = nodeTiles < 296 ? nodeTiles : 296;
    const int u1Grid   = nodeTiles < 296 ? nodeTiles : 296;
    const int u2Grid   = nodeTiles < 592 ? nodeTiles : 592;

    dim3 gPQ(pqGrid, 2);

    k_detect<<<1, 32>>>((const unsigned int*)ei);
    k_conv<<<(2 * E + 255) / 256, 256>>>(ei, 2 * E, N);
    k_pq<<<gPQ, 256, sm_pq>>>(h, W1, b1, N);
    k_edge<<<edgeGrid, 256, sm_e>>>(coords, W1, W2, b2, E);
    k_u1<<<u1Grid, 256, sm_u1>>>(h, U1, c1, N);
    k_u2<<<u2Grid, 256, sm_u2>>>(h, U2, c2, out, N);
}

// round 10
// speedup vs baseline: 1.3138x; 1.3138x over previous
#include <cuda_runtime.h>
#include <cuda_fp16.h>
#include <math.h>

#define DD 128
#define MAXN 50000
#define MAXE 800000

__device__ unsigned g_Ph[MAXN * 64];   // A @ h_n           (f16x2 pairs)
__device__ unsigned g_Qh[MAXN * 64];   // B @ h_n + b1      (f16x2 pairs)
__device__ float    g_agg[MAXN * DD];  // scatter-add target (fp32)
__device__ unsigned g_th[MAXN * 64];   // silu(U1@[h;agg]+c1) (f16x2 pairs)
__device__ int      g_eidx[2 * MAXE];  // normalized int32 edge index
__device__ int      g_is64;            // dtype probe result

__device__ __forceinline__ float fast_silu(float x) {
    float hx = 0.5f * x, t;
    asm("tanh.approx.f32 %0, %1;" : "=f"(t) : "f"(hx));
    return fmaf(hx, t, hx);
}

__device__ __forceinline__ void red_add_v2(float* p, float a, float b) {
    asm volatile("red.global.add.v2.f32 [%0], {%1,%2};"
                 :: "l"(p), "f"(a), "f"(b) : "memory");
}

// pack (lo, hi) fp32 -> f16x2
__device__ __forceinline__ unsigned f16x2(float lo, float hi) {
    unsigned r;
    asm("cvt.rn.f16x2.f32 %0, %1, %2;" : "=r"(r) : "f"(hi), "f"(lo));
    return r;
}
__device__ __forceinline__ float2 unpackh2(unsigned u) {
    __half2 h = *reinterpret_cast<const __half2*>(&u);
    return __half22float2(h);
}

// m16n8k16 f16 mma: A row-major (16x16), B col-major (16x8), fp32 accum
__device__ __forceinline__ void mma_f16(float* c, const unsigned* a,
                                        unsigned b0, unsigned b1) {
    asm volatile(
        "mma.sync.aligned.m16n8k16.row.col.f32.f16.f16.f32 "
        "{%0,%1,%2,%3}, {%4,%5,%6,%7}, {%8,%9}, {%0,%1,%2,%3};"
        : "+f"(c[0]), "+f"(c[1]), "+f"(c[2]), "+f"(c[3])
        : "r"(a[0]), "r"(a[1]), "r"(a[2]), "r"(a[3]), "r"(b0), "r"(b1));
}
__device__ __forceinline__ void mma_f16s(float* c, unsigned a0, unsigned a1,
                                         unsigned a2, unsigned a3,
                                         unsigned b0, unsigned b1) {
    asm volatile(
        "mma.sync.aligned.m16n8k16.row.col.f32.f16.f16.f32 "
        "{%0,%1,%2,%3}, {%4,%5,%6,%7}, {%8,%9}, {%0,%1,%2,%3};"
        : "+f"(c[0]), "+f"(c[1]), "+f"(c[2]), "+f"(c[3])
        : "r"(a0), "r"(a1), "r"(a2), "r"(a3), "r"(b0), "r"(b1));
}

// ldmatrix x4: loads 4 8x8 b16 quads; lane groups 0-7/8-15/16-23/24-31 give row ptrs
__device__ __forceinline__ void ldsm_x4(unsigned* r, unsigned addr) {
    asm volatile("ldmatrix.sync.aligned.m8n8.x4.shared.b16 {%0,%1,%2,%3}, [%4];"
                 : "=r"(r[0]), "=r"(r[1]), "=r"(r[2]), "=r"(r[3]) : "r"(addr));
}

// ---------------------------------------------------------------------------
// Kernel 0a/0b: edge_index dtype probe + normalize to int32
// ---------------------------------------------------------------------------
__global__ void k_detect(const unsigned int* __restrict__ p) {
    if (threadIdx.x == 0) {
        int is64 = 1;
        for (int i = 0; i < 512; i++)
            if (p[2 * i + 1] != 0u) { is64 = 0; break; }
        g_is64 = is64;
    }
}

__global__ __launch_bounds__(256) void k_conv(const void* __restrict__ ei,
                                              int twoE, int N) {
    int i = blockIdx.x * blockDim.x + threadIdx.x;
    if (i >= twoE) return;
    long long v = g_is64 ? ((const long long*)ei)[i]
                         : (long long)((const int*)ei)[i];
    if (v < 0) v = 0;
    if (v >= N) v = N - 1;
    g_eidx[i] = (int)v;
}

// ---------------------------------------------------------------------------
// Kernel 1: by=0 -> Ph = A @ h (f16x2);  by=1 -> Qh = B @ h + b1 (f16x2)
// fp16 MMA, 64-node tiles, 256 thr, persistent, 4 CTAs/SM.  (round-8 form)
// ---------------------------------------------------------------------------
__global__ __launch_bounds__(256, 4) void k_pq(const float* __restrict__ h,
                                               const float* __restrict__ W1,
                                               const float* __restrict__ b1, int N) {
    extern __shared__ float sm[];
    unsigned* Wu = (unsigned*)sm;          // [128 d][68] half2 pairs of k
    unsigned* Xu = (unsigned*)sm + 8704;   // [64 n][68]
    const int t = threadIdx.x;
    const int by = blockIdx.y;

    for (int idx = t; idx < DD * 64; idx += 256) {
        int d = idx >> 6, kk = idx & 63;
        const float* wr = W1 + (size_t)d * 257 + by * DD + 2 * kk;
        Wu[d * 68 + kk] = f16x2(wr[0], wr[1]);
    }
    const int dp = t & 63, q = t >> 6;
    const int warp = t >> 5, lane = t & 31, g = lane >> 2, tg = lane & 3;
    const int mt = warp >> 1, nh = warp & 1;
    const int row0 = mt * 16 + g;

    const int numTiles = (N + 63) >> 6;
    for (int tile = blockIdx.x; tile < numTiles; tile += gridDim.x) {
        const int n0 = tile << 6;
        __syncthreads();
#pragma unroll 4
        for (int e2 = 0; e2 < 16; e2++) {
            int row = q * 16 + e2;
            int node = n0 + row;
            unsigned v = 0;
            if (node < N) {
                float2 hv = *(const float2*)(h + (size_t)node * DD + 2 * dp);
                v = f16x2(hv.x, hv.y);
            }
            Xu[row * 68 + dp] = v;
        }
        __syncthreads();

        float acc[8][4] = {};
#pragma unroll
        for (int ks = 0; ks < 8; ks++) {
            const int kk = ks * 8 + tg;
            unsigned a0 = Xu[row0 * 68 + kk];
            unsigned a1 = Xu[(row0 + 8) * 68 + kk];
            unsigned a2 = Xu[row0 * 68 + kk + 4];
            unsigned a3 = Xu[(row0 + 8) * 68 + kk + 4];
#pragma unroll
            for (int nt = 0; nt < 8; nt++) {
                const int d = nh * 64 + nt * 8 + g;
                mma_f16s(acc[nt], a0, a1, a2, a3, Wu[d * 68 + kk], Wu[d * 68 + kk + 4]);
            }
        }

        const int node0 = n0 + row0, node1 = node0 + 8;
        unsigned* dstArr = by ? g_Qh : g_Ph;
#pragma unroll
        for (int nt = 0; nt < 8; nt++) {
            int d = nh * 64 + nt * 8 + 2 * tg;
            float ba = 0.f, bb = 0.f;
            if (by) { ba = b1[d]; bb = b1[d + 1]; }
            if (node0 < N)
                dstArr[(size_t)node0 * 64 + (d >> 1)] = f16x2(acc[nt][0] + ba, acc[nt][1] + bb);
            if (node1 < N)
                dstArr[(size_t)node1 * 64 + (d >> 1)] = f16x2(acc[nt][2] + ba, acc[nt][3] + bb);
        }
    }
}

// ---------------------------------------------------------------------------
// Kernel 2 (edge): fp16 MMA, 64-edge tiles, 256 thr, 4 CTAs/SM (round-8 env).
// NEW: ldmatrix.x4 fragment loads + 2m x 4n warp layout.
//   warp = 2 m16-tiles (32 edges) x 32 d; per ks: 4 LDSM.x4 + 16 MMA.
// smem words: Wu[0,8704) Xu[8704,13056) b2s[13056,13184) sdist[13184,13248)
//             ss[13248,13312) sr[13312,13376)
// ---------------------------------------------------------------------------
__global__ __launch_bounds__(256, 4) void k_edge(const float* __restrict__ coords,
                                                 const float* __restrict__ W1,
                                                 const float* __restrict__ W2,
                                                 const float* __restrict__ b2, int E) {
    extern __shared__ float sm[];
    unsigned* Wu = (unsigned*)sm;            // [128 d][68] half2
    unsigned* Xu = (unsigned*)sm + 8704;     // [64 e][68] half2
    float* b2s   = sm + 13056;               // [128]
    float* sdist = sm + 13184;               // [64]
    int* ss = (int*)(sm + 13248);            // [64]
    int* sr = (int*)(sm + 13312);            // [64]
    const int t = threadIdx.x;

    for (int idx = t; idx < DD * 64; idx += 256) {
        int d = idx >> 6, kk = idx & 63;
        Wu[d * 68 + kk] = f16x2(W2[d * DD + 2 * kk], W2[d * DD + 2 * kk + 1]);
    }
    if (t < DD) b2s[t] = b2[t];

    const int dp = t & 63, q = t >> 6;       // stage1: feature pair x edge quarter
    const float wd0 = W1[(2 * dp) * 257 + 256];
    const float wd1 = W1[(2 * dp + 1) * 257 + 256];

    const int warp = t >> 5, lane = t & 31, g = lane >> 2, tg = lane & 3;
    const int mg = warp >> 2, ng = warp & 3; // 2 m-groups x 4 n-groups
    const int lr = lane & 7, qi = lane >> 3;

    // ldmatrix lane addresses (byte, shared space), bumped +32B per ks.
    // A quads: (rows lo, w0) (rows hi, w0) (rows lo, w4) (rows hi, w4)
    const unsigned xuB = (unsigned)__cvta_generic_to_shared(Xu);
    const unsigned wuB = (unsigned)__cvta_generic_to_shared(Wu);
    const int arow = mg * 32 + ((qi & 1) ? 8 : 0) + lr;
    const int awof = (qi >= 2) ? 4 : 0;
    const unsigned aAddr0 = xuB + (unsigned)(arow * 68 + awof) * 4u;
    const unsigned aAddr1 = aAddr0 + 16u * 68u * 4u;     // second m-tile (+16 rows)
    // B quads: (d lo, w0) (d lo, w4) (d hi, w0) (d hi, w4)
    const int brow = ng * 32 + ((qi >= 2) ? 8 : 0) + lr;
    const int bwof = (qi & 1) ? 4 : 0;
    const unsigned bAddr0 = wuB + (unsigned)(brow * 68 + bwof) * 4u;
    const unsigned bAddr1 = bAddr0 + 16u * 68u * 4u;     // second nt-pair (+16 d)

    const int numTiles = (E + 63) >> 6;
    for (int tile = blockIdx.x; tile < numTiles; tile += gridDim.x) {
        const int e0 = tile << 6;
        __syncthreads();
        if (t < 64) {
            int e = e0 + t;
            int s = 0, r = 0;
            float dist = 0.f;
            if (e < E) {
                s = g_eidx[e];
                r = g_eidx[E + e];
                float dx = coords[s * 3 + 0] - coords[r * 3 + 0];
                float dy = coords[s * 3 + 1] - coords[r * 3 + 1];
                float dz = coords[s * 3 + 2] - coords[r * 3 + 2];
                dist = sqrtf(fmaf(dx, dx, fmaf(dy, dy, dz * dz)));
            }
            ss[t] = s; sr[t] = r; sdist[t] = dist;
        }
        __syncthreads();

        // Stage 1: 16 edges x feature pair (2dp, 2dp+1), f16x2 gathers
#pragma unroll 4
        for (int e2 = 0; e2 < 16; e2++) {
            int e = q * 16 + e2;
            int s = ss[e], r = sr[e];
            float dist = sdist[e];
            float2 p  = unpackh2(g_Ph[(size_t)s * 64 + dp]);
            float2 qq = unpackh2(g_Qh[(size_t)r * 64 + dp]);
            float zx = fast_silu(p.x + qq.x + dist * wd0);
            float zy = fast_silu(p.y + qq.y + dist * wd1);
            Xu[e * 68 + dp] = f16x2(zx, zy);
        }
        __syncthreads();

        // acc[mi][p2]: m-tile mi, d-block p2 (d = ng*32 + p2*8); bias folded in.
        float acc[2][4][4];
#pragma unroll
        for (int p2 = 0; p2 < 4; p2++) {
            int d = ng * 32 + p2 * 8 + 2 * tg;
            float ba = b2s[d], bb = b2s[d + 1];
#pragma unroll
            for (int mi = 0; mi < 2; mi++) {
                acc[mi][p2][0] = ba; acc[mi][p2][1] = bb;
                acc[mi][p2][2] = ba; acc[mi][p2][3] = bb;
            }
        }
#pragma unroll
        for (int ks = 0; ks < 8; ks++) {
            const unsigned ofs = (unsigned)ks * 32u;
            unsigned a0[4], a1[4], b0[4], b1[4];
            ldsm_x4(a0, aAddr0 + ofs);
            ldsm_x4(a1, aAddr1 + ofs);
            ldsm_x4(b0, bAddr0 + ofs);
            ldsm_x4(b1, bAddr1 + ofs);
            // b0 = {b0lo,b1lo,b0hi,b1hi} for d-blocks p2=0,1; b1 for p2=2,3
            mma_f16(acc[0][0], a0, b0[0], b0[1]);
            mma_f16(acc[0][1], a0, b0[2], b0[3]);
            mma_f16(acc[0][2], a0, b1[0], b1[1]);
            mma_f16(acc[0][3], a0, b1[2], b1[3]);
            mma_f16(acc[1][0], a1, b0[0], b0[1]);
            mma_f16(acc[1][1], a1, b0[2], b0[3]);
            mma_f16(acc[1][2], a1, b1[0], b1[1]);
            mma_f16(acc[1][3], a1, b1[2], b1[3]);
        }

        // Epilogue: silu + red.v2 scatter; 4 edge-rows per thread
#pragma unroll
        for (int mi = 0; mi < 2; mi++) {
            const int er0 = mg * 32 + mi * 16 + g;
            const int er1 = er0 + 8;
            const bool ok0 = (e0 + er0) < E;
            const bool ok1 = (e0 + er1) < E;
            const int r0 = sr[er0], r1 = sr[er1];
#pragma unroll
            for (int p2 = 0; p2 < 4; p2++) {
                int d = ng * 32 + p2 * 8 + 2 * tg;
                if (ok0)
                    red_add_v2(g_agg + (size_t)r0 * DD + d,
                               fast_silu(acc[mi][p2][0]), fast_silu(acc[mi][p2][1]));
                if (ok1)
                    red_add_v2(g_agg + (size_t)r1 * DD + d,
                               fast_silu(acc[mi][p2][2]), fast_silu(acc[mi][p2][3]));
            }
        }
    }
}

// ---------------------------------------------------------------------------
// Kernel 3: th = f16x2(silu(U1 @ [h ; agg] + c1)), K=256. (round-8 form)
// ---------------------------------------------------------------------------
__global__ __launch_bounds__(256, 2) void k_u1(const float* __restrict__ h,
                                               const float* __restrict__ U1,
                                               const float* __restrict__ c1, int N) {
    extern __shared__ float sm[];
    unsigned* Wu = (unsigned*)sm;            // [128 d][140]
    unsigned* Xu = (unsigned*)sm + 128 * 140;// [64 n][140]
    const int t = threadIdx.x;

    for (int idx = t; idx < DD * 128; idx += 256) {
        int d = idx >> 7, kk = idx & 127;
        Wu[d * 140 + kk] = f16x2(U1[(size_t)d * 256 + 2 * kk], U1[(size_t)d * 256 + 2 * kk + 1]);
    }
    const int dp = t & 63, q = t >> 6;
    const int warp = t >> 5, lane = t & 31, g = lane >> 2, tg = lane & 3;
    const int mt = warp >> 1, nh = warp & 1;
    const int row0 = mt * 16 + g;

    const int numTiles = (N + 63) >> 6;
    for (int tile = blockIdx.x; tile < numTiles; tile += gridDim.x) {
        const int n0 = tile << 6;
        __syncthreads();
#pragma unroll 4
        for (int e2 = 0; e2 < 16; e2++) {
            int row = q * 16 + e2;
            int node = n0 + row;
            unsigned vh = 0, va = 0;
            if (node < N) {
                float2 hv = *(const float2*)(h + (size_t)node * DD + 2 * dp);
                float2 av = *(const float2*)(g_agg + (size_t)node * DD + 2 * dp);
                vh = f16x2(hv.x, hv.y);
                va = f16x2(av.x, av.y);
            }
            Xu[row * 140 + dp] = vh;
            Xu[row * 140 + 64 + dp] = va;
        }
        __syncthreads();

        float acc[8][4] = {};
#pragma unroll
        for (int ks = 0; ks < 16; ks++) {
            const int kk = ks * 8 + tg;
            unsigned a0 = Xu[row0 * 140 + kk];
            unsigned a1 = Xu[(row0 + 8) * 140 + kk];
            unsigned a2 = Xu[row0 * 140 + kk + 4];
            unsigned a3 = Xu[(row0 + 8) * 140 + kk + 4];
#pragma unroll
            for (int nt = 0; nt < 8; nt++) {
                const int d = nh * 64 + nt * 8 + g;
                mma_f16s(acc[nt], a0, a1, a2, a3, Wu[d * 140 + kk], Wu[d * 140 + kk + 4]);
            }
        }

        const int node0 = n0 + row0, node1 = node0 + 8;
#pragma unroll
        for (int nt = 0; nt < 8; nt++) {
            int d = nh * 64 + nt * 8 + 2 * tg;
            float ca = c1[d], cb = c1[d + 1];
            if (node0 < N)
                g_th[(size_t)node0 * 64 + (d >> 1)] =
                    f16x2(fast_silu(acc[nt][0] + ca), fast_silu(acc[nt][1] + cb));
            if (node1 < N)
                g_th[(size_t)node1 * 64 + (d >> 1)] =
                    f16x2(fast_silu(acc[nt][2] + ca), fast_silu(acc[nt][3] + cb));
        }
    }
}

// ---------------------------------------------------------------------------
// Kernel 4: out = h + U2 @ t + c2, K=128. fp16 MMA, 4 CTAs/SM. (round-8 form)
// ---------------------------------------------------------------------------
__global__ __launch_bounds__(256, 4) void k_u2(const float* __restrict__ h,
                                               const float* __restrict__ U2,
                                               const float* __restrict__ c2,
                                               float* __restrict__ out, int N) {
    extern __shared__ float sm[];
    unsigned* Wu = (unsigned*)sm;          // [128][68]
    unsigned* Xu = (unsigned*)sm + 8704;   // [64][68]
    const int t = threadIdx.x;

    for (int idx = t; idx < DD * 64; idx += 256) {
        int d = idx >> 6, kk = idx & 63;
        Wu[d * 68 + kk] = f16x2(U2[(size_t)d * DD + 2 * kk], U2[(size_t)d * DD + 2 * kk + 1]);
    }
    const int dp = t & 63, q = t >> 6;
    const int warp = t >> 5, lane = t & 31, g = lane >> 2, tg = lane & 3;
    const int mt = warp >> 1, nh = warp & 1;
    const int row0 = mt * 16 + g;

    const int numTiles = (N + 63) >> 6;
    for (int tile = blockIdx.x; tile < numTiles; tile += gridDim.x) {
        const int n0 = tile << 6;
        __syncthreads();
#pragma unroll 4
        for (int e2 = 0; e2 < 16; e2++) {
            int row = q * 16 + e2;
            int node = n0 + row;
            Xu[row * 68 + dp] = (node < N) ? g_th[(size_t)node * 64 + dp] : 0u;
        }
        __syncthreads();

        float acc[8][4] = {};
#pragma unroll
        for (int ks = 0; ks < 8; ks++) {
            const int kk = ks * 8 + tg;
            unsigned a0 = Xu[row0 * 68 + kk];
            unsigned a1 = Xu[(row0 + 8) * 68 + kk];
            unsigned a2 = Xu[row0 * 68 + kk + 4];
            unsigned a3 = Xu[(row0 + 8) * 68 + kk + 4];
#pragma unroll
            for (int nt = 0; nt < 8; nt++) {
                const int d = nh * 64 + nt * 8 + g;
                mma_f16s(acc[nt], a0, a1, a2, a3, Wu[d * 68 + kk], Wu[d * 68 + kk + 4]);
            }
        }

        const int node0 = n0 + row0, node1 = node0 + 8;
#pragma unroll
        for (int nt = 0; nt < 8; nt++) {
            int d = nh * 64 + nt * 8 + 2 * tg;
            float ca = c2[d], cb = c2[d + 1];
            if (node0 < N) {
                float2 hv = *(const float2*)(h + (size_t)node0 * DD + d);
                *(float2*)(out + (size_t)node0 * DD + d) =
                    make_float2(hv.x + acc[nt][0] + ca, hv.y + acc[nt][1] + cb);
            }
            if (node1 < N) {
                float2 hv = *(const float2*)(h + (size_t)node1 * DD + d);
                *(float2*)(out + (size_t)node1 * DD + d) =
                    make_float2(hv.x + acc[nt][2] + ca, hv.y + acc[nt][3] + cb);
            }
        }
    }
}

// ---------------------------------------------------------------------------
extern "C" void kernel_launch(void* const* d_in, const int* in_sizes, int n_in,
                              void* d_out, int out_size) {
    const float* h        = (const float*)d_in[0];
    const float* coords   = (const float*)d_in[1];
    const void*  ei       = d_in[2];
    const float* W1       = (const float*)d_in[3];
    const float* b1       = (const float*)d_in[4];
    const float* W2       = (const float*)d_in[5];
    const float* b2       = (const float*)d_in[6];
    const float* U1       = (const float*)d_in[7];
    const float* c1       = (const float*)d_in[8];
    const float* U2       = (const float*)d_in[9];
    const float* c2       = (const float*)d_in[10];
    float* out = (float*)d_out;

    const int N = in_sizes[0] / DD;
    const int E = in_sizes[2] / 2;

    const size_t sm_pq = (8704 + 64 * 68) * sizeof(unsigned);
    const size_t sm_e  = 13376 * sizeof(float);                          // 53.5 KB
    const size_t sm_u1 = (128 * 140 + 64 * 140) * sizeof(unsigned);      // 105 KB
    const size_t sm_u2 = (8704 + 64 * 68) * sizeof(unsigned);

    cudaFuncSetAttribute(k_pq,   cudaFuncAttributeMaxDynamicSharedMemorySize, (int)sm_pq);
    cudaFuncSetAttribute(k_edge, cudaFuncAttributeMaxDynamicSharedMemorySize, (int)sm_e);
    cudaFuncSetAttribute(k_u1,   cudaFuncAttributeMaxDynamicSharedMemorySize, (int)sm_u1);
    cudaFuncSetAttribute(k_u2,   cudaFuncAttributeMaxDynamicSharedMemorySize, (int)sm_u2);

    void* aggPtr = nullptr;
    cudaGetSymbolAddress(&aggPtr, g_agg);
    cudaMemsetAsync(aggPtr, 0, (size_t)N * DD * sizeof(float));

    const int nodeTiles = (N + 63) / 64;
    const int edgeTiles = (E + 63) / 64;
    const int edgeGrid = edgeTiles < 592 ? edgeTiles : 592;  // 4 CTAs/SM persistent
    const int pqGrid   = nodeTiles < 296 ? nodeTiles : 296;
    const int u1Grid   = nodeTiles < 296 ? nodeTiles : 296;
    const int u2Grid   = nodeTiles < 592 ? nodeTiles : 592;

    dim3 gPQ(pqGrid, 2);

    k_detect<<<1, 32>>>((const unsigned int*)ei);
    k_conv<<<(2 * E + 255) / 256, 256>>>(ei, 2 * E, N);
    k_pq<<<gPQ, 256, sm_pq>>>(h, W1, b1, N);
    k_edge<<<edgeGrid, 256, sm_e>>>(coords, W1, W2, b2, E);
    k_u1<<<u1Grid, 256, sm_u1>>>(h, U1, c1, N);
    k_u2<<<u2Grid, 256, sm_u2>>>(h, U2, c2, out, N);
}